// round 7
// baseline (speedup 1.0000x reference)
#include <cuda_runtime.h>
#include <cstdint>

// Problem constants (fixed: NUM_VARS=6, ORDER=3 -> M=84; J=K=2048)
#define NUM_VARS   6
#define M_MONO     84
#define ROWS_TOTAL (2048 * 2048)
#define TILE       32                      // rows (outputs) per chunk
#define NCHUNKS    (ROWS_TOTAL / TILE)     // 131072
#define CHUNK_FLOATS (TILE * M_MONO)       // 2688
#define CHUNK_BYTES  (CHUNK_FLOATS * 4)    // 10752
#define THREADS    32                      // one warp per block
#define NSTAGES    4                       // 4-deep TMA ring, 3 outstanding
#define GRID_BLOCKS 740                    // 148 SMs x 5 resident blocks
#define BASE_ITERS (NCHUNKS / GRID_BLOCKS)               // 177
#define REM_BLOCKS (NCHUNKS - BASE_ITERS * GRID_BLOCKS)  // 92

__device__ __forceinline__ uint32_t smem_u32(const void* p) {
    uint32_t a;
    asm("{ .reg .u64 t; cvta.to.shared.u64 t, %1; cvt.u32.u64 %0, t; }" : "=r"(a) : "l"(p));
    return a;
}

__device__ __forceinline__ void mbar_init(uint32_t mbar, uint32_t count) {
    asm volatile("mbarrier.init.shared.b64 [%0], %1;" :: "r"(mbar), "r"(count) : "memory");
}
__device__ __forceinline__ void mbar_expect_tx(uint32_t mbar, uint32_t bytes) {
    asm volatile("mbarrier.arrive.expect_tx.shared.b64 _, [%0], %1;" :: "r"(mbar), "r"(bytes) : "memory");
}
__device__ __forceinline__ void mbar_wait(uint32_t mbar, uint32_t parity) {
    uint32_t done;
    asm volatile(
        "{\n\t.reg .pred p;\n\t"
        "mbarrier.try_wait.parity.acquire.cta.shared::cta.b64 p, [%1], %2;\n\t"
        "selp.b32 %0, 1, 0, p;\n\t}"
        : "=r"(done) : "r"(mbar), "r"(parity) : "memory");
    if (!done) {
        asm volatile(
            "{\n\t.reg .pred P1;\n\t"
            "W%=:\n\t"
            "mbarrier.try_wait.parity.acquire.cta.shared::cta.b64 P1, [%0], %1, 0x989680;\n\t"
            "@P1 bra.uni D%=;\n\t"
            "bra.uni W%=;\n\t"
            "D%=:\n\t}"
            :: "r"(mbar), "r"(parity) : "memory");
    }
}
__device__ __forceinline__ void tma_bulk_1d(uint32_t dst_smem, const void* src_gmem,
                                            uint32_t bytes, uint32_t mbar) {
    asm volatile(
        "cp.async.bulk.shared::cta.global.mbarrier::complete_tx::bytes [%0], [%1], %2, [%3];"
        :: "r"(dst_smem), "l"(src_gmem), "r"(bytes), "r"(mbar) : "memory");
}

__global__ __launch_bounds__(THREADS) void monomial_matvec_kernel(
    const float* __restrict__ x,        // (6,)
    const float* __restrict__ coeffs,   // (ROWS_TOTAL, 84) contiguous
    float* __restrict__ out)            // (ROWS_TOTAL)
{
    __shared__ __align__(16) float buf[NSTAGES][CHUNK_FLOATS];  // 4 x 10752 B
    __shared__ float sv[M_MONO];
    __shared__ __align__(8) unsigned long long mbar_storage[NSTAGES];

    const int tid = threadIdx.x;   // lane id (single warp)
    const int bid = blockIdx.x;

    const uint32_t mbase = smem_u32(&mbar_storage[0]);

    // Contiguous balanced partition: block b owns chunks [start, start+nIters).
    const int extra  = (bid < REM_BLOCKS);
    const int start  = bid * BASE_ITERS + (extra ? bid : REM_BLOCKS);
    const int nIters = BASE_ITERS + extra;

    // Lane 0: init barriers, kick off 3 prologue TMAs, then build the
    // monomial vector v (combinations_with_replacement order) while the
    // first TMA is in flight.
    if (tid == 0) {
        #pragma unroll
        for (int s = 0; s < NSTAGES; s++) mbar_init(mbase + 8 * s, 1);
        asm volatile("fence.proxy.async.shared::cta;" ::: "memory");
        #pragma unroll
        for (int k = 0; k < NSTAGES - 1; k++) {
            if (k < nIters) {
                const uint32_t mb = mbase + 8 * k;
                const long long c = (long long)start + k;
                mbar_expect_tx(mb, CHUNK_BYTES);
                tma_bulk_1d(smem_u32(&buf[k][0]), coeffs + c * CHUNK_FLOATS,
                            CHUNK_BYTES, mb);
            }
        }
        float xv[NUM_VARS];
        #pragma unroll
        for (int i = 0; i < NUM_VARS; i++) xv[i] = x[i];
        int idx = 0;
        sv[idx++] = 1.0f;
        #pragma unroll
        for (int a = 0; a < NUM_VARS; a++) sv[idx++] = xv[a];
        #pragma unroll
        for (int a = 0; a < NUM_VARS; a++)
            #pragma unroll
            for (int b = a; b < NUM_VARS; b++) sv[idx++] = xv[a] * xv[b];
        #pragma unroll
        for (int a = 0; a < NUM_VARS; a++)
            #pragma unroll
            for (int b = a; b < NUM_VARS; b++)
                #pragma unroll
                for (int c = b; c < NUM_VARS; c++) sv[idx++] = xv[a] * xv[b] * xv[c];
    }
    __syncwarp();   // sv ready; mbarriers initialized before any wait

    for (int i = 0; i < nIters; i++) {
        const int s  = i & (NSTAGES - 1);
        const int ph = (i >> 2) & 1;
        mbar_wait(mbase + 8 * s, ph);

        // Dot this lane's 84-float row against v.
        // Row stride = 84 words: lane bank bases (20*l mod 32) form a
        // permutation per 8-lane LDS.128 phase -> conflict-free.
        const float4* __restrict__ row = (const float4*)&buf[s][tid * M_MONO];
        float acc0 = 0.f, acc1 = 0.f, acc2 = 0.f, acc3 = 0.f;
        #pragma unroll
        for (int k = 0; k < M_MONO / 4; k++) {
            float4 q = row[k];
            acc0 = fmaf(q.x, sv[4 * k + 0], acc0);
            acc1 = fmaf(q.y, sv[4 * k + 1], acc1);
            acc2 = fmaf(q.z, sv[4 * k + 2], acc2);
            acc3 = fmaf(q.w, sv[4 * k + 3], acc3);
        }
        const long long c = (long long)start + i;
        out[c * TILE + tid] = (acc0 + acc1) + (acc2 + acc3);

        __syncwarp();  // whole warp done reading buf[s]

        // Refill: chunk i+3 goes into stage (i+3)&3 == (i-1)&3, which was
        // consumed at iteration i-1. Keeps 3 chunks outstanding steady-state.
        if (tid == 0 && (i + NSTAGES - 1) < nIters) {
            asm volatile("fence.proxy.async.shared::cta;" ::: "memory");
            const int sn = (i + NSTAGES - 1) & (NSTAGES - 1);
            const long long cn = (long long)start + (i + NSTAGES - 1);
            const uint32_t mb = mbase + 8 * sn;
            mbar_expect_tx(mb, CHUNK_BYTES);
            tma_bulk_1d(smem_u32(&buf[sn][0]), coeffs + cn * CHUNK_FLOATS,
                        CHUNK_BYTES, mb);
        }
    }
}

extern "C" void kernel_launch(void* const* d_in, const int* in_sizes, int n_in,
                              void* d_out, int out_size) {
    const float* x      = (const float*)d_in[0];   // (6,)
    const float* coeffs = (const float*)d_in[1];   // (2048, 2048, 84)
    float* out = (float*)d_out;                    // (2048, 2048)

    monomial_matvec_kernel<<<GRID_BLOCKS, THREADS>>>(x, coeffs, out);
}

// round 8
// speedup vs baseline: 1.0283x; 1.0283x over previous
#include <cuda_runtime.h>
#include <cstdint>

// Problem constants (fixed: NUM_VARS=6, ORDER=3 -> M=84; J=K=2048)
#define NUM_VARS   6
#define M_MONO     84
#define ROWS_TOTAL (2048 * 2048)
#define TILE       64                      // rows (outputs) per chunk
#define NCHUNKS    (ROWS_TOTAL / TILE)     // 65536
#define CHUNK_FLOATS (TILE * M_MONO)       // 5376
#define CHUNK_BYTES  (CHUNK_FLOATS * 4)    // 21504
#define THREADS    64
#define GRID_BLOCKS 740                    // 148 SMs x 5 resident blocks (measured-best)

__device__ __forceinline__ uint32_t smem_u32(const void* p) {
    uint32_t a;
    asm("{ .reg .u64 t; cvta.to.shared.u64 t, %1; cvt.u32.u64 %0, t; }" : "=r"(a) : "l"(p));
    return a;
}

__device__ __forceinline__ void mbar_init(uint32_t mbar, uint32_t count) {
    asm volatile("mbarrier.init.shared.b64 [%0], %1;" :: "r"(mbar), "r"(count) : "memory");
}
__device__ __forceinline__ void mbar_expect_tx(uint32_t mbar, uint32_t bytes) {
    asm volatile("mbarrier.arrive.expect_tx.shared.b64 _, [%0], %1;" :: "r"(mbar), "r"(bytes) : "memory");
}
__device__ __forceinline__ void mbar_wait(uint32_t mbar, uint32_t parity) {
    uint32_t done;
    asm volatile(
        "{\n\t.reg .pred p;\n\t"
        "mbarrier.try_wait.parity.acquire.cta.shared::cta.b64 p, [%1], %2;\n\t"
        "selp.b32 %0, 1, 0, p;\n\t}"
        : "=r"(done) : "r"(mbar), "r"(parity) : "memory");
    if (!done) {
        asm volatile(
            "{\n\t.reg .pred P1;\n\t"
            "W%=:\n\t"
            "mbarrier.try_wait.parity.acquire.cta.shared::cta.b64 P1, [%0], %1, 0x989680;\n\t"
            "@P1 bra.uni D%=;\n\t"
            "bra.uni W%=;\n\t"
            "D%=:\n\t}"
            :: "r"(mbar), "r"(parity) : "memory");
    }
}
__device__ __forceinline__ void tma_bulk_1d(uint32_t dst_smem, const void* src_gmem,
                                            uint32_t bytes, uint32_t mbar) {
    asm volatile(
        "cp.async.bulk.shared::cta.global.mbarrier::complete_tx::bytes [%0], [%1], %2, [%3];"
        :: "r"(dst_smem), "l"(src_gmem), "r"(bytes), "r"(mbar) : "memory");
}

__global__ __launch_bounds__(THREADS) void monomial_matvec_kernel(
    const float* __restrict__ x,        // (6,)
    const float* __restrict__ coeffs,   // (ROWS_TOTAL, 84) contiguous
    float* __restrict__ out)            // (ROWS_TOTAL)
{
    __shared__ __align__(16) float buf[2][CHUNK_FLOATS];  // 2 x 21504 B
    __shared__ float sv[M_MONO];
    __shared__ __align__(8) unsigned long long mbar_storage[2];

    const int tid = threadIdx.x;
    const int bid = blockIdx.x;

    const uint32_t mb0 = smem_u32(&mbar_storage[0]);
    const uint32_t mb1 = mb0 + 8;

    // chunks handled by this block: c = bid + i * GRID_BLOCKS
    const int nIters = (NCHUNKS - bid + GRID_BLOCKS - 1) / GRID_BLOCKS;

    // Thread 0: init barriers, kick off the prologue TMAs, then build the
    // monomial vector v (combinations_with_replacement order) while the
    // first TMA is in flight.
    if (tid == 0) {
        mbar_init(mb0, 1);
        mbar_init(mb1, 1);
        asm volatile("fence.proxy.async.shared::cta;" ::: "memory");
        #pragma unroll
        for (int k = 0; k < 2; k++) {
            if (k < nIters) {
                const uint32_t mb = (k == 0) ? mb0 : mb1;
                const long long c = (long long)bid + (long long)k * GRID_BLOCKS;
                mbar_expect_tx(mb, CHUNK_BYTES);
                tma_bulk_1d(smem_u32(&buf[k][0]), coeffs + c * CHUNK_FLOATS,
                            CHUNK_BYTES, mb);
            }
        }
        float xv[NUM_VARS];
        #pragma unroll
        for (int i = 0; i < NUM_VARS; i++) xv[i] = x[i];
        int idx = 0;
        sv[idx++] = 1.0f;
        #pragma unroll
        for (int a = 0; a < NUM_VARS; a++) sv[idx++] = xv[a];
        #pragma unroll
        for (int a = 0; a < NUM_VARS; a++)
            #pragma unroll
            for (int b = a; b < NUM_VARS; b++) sv[idx++] = xv[a] * xv[b];
        #pragma unroll
        for (int a = 0; a < NUM_VARS; a++)
            #pragma unroll
            for (int b = a; b < NUM_VARS; b++)
                #pragma unroll
                for (int c = b; c < NUM_VARS; c++) sv[idx++] = xv[a] * xv[b] * xv[c];
    }
    __syncthreads();   // sv ready; mbarriers initialized before any wait

    for (int i = 0; i < nIters; i++) {
        const int b  = i & 1;
        const int ph = (i >> 1) & 1;
        mbar_wait(b ? mb1 : mb0, ph);

        // Dot this thread's 84-float row against v.
        // Row stride = 84 words: lane bank bases (20*l mod 32) form a
        // permutation per 8-lane LDS.128 phase -> conflict-free.
        const float4* __restrict__ row = (const float4*)&buf[b][tid * M_MONO];
        float acc0 = 0.f, acc1 = 0.f, acc2 = 0.f, acc3 = 0.f;
        #pragma unroll
        for (int k = 0; k < M_MONO / 4; k++) {
            float4 q = row[k];
            acc0 = fmaf(q.x, sv[4 * k + 0], acc0);
            acc1 = fmaf(q.y, sv[4 * k + 1], acc1);
            acc2 = fmaf(q.z, sv[4 * k + 2], acc2);
            acc3 = fmaf(q.w, sv[4 * k + 3], acc3);
        }
        const long long c = (long long)bid + (long long)i * GRID_BLOCKS;
        out[c * TILE + tid] = (acc0 + acc1) + (acc2 + acc3);

        __syncthreads();  // all threads done reading buf[b]

        if (tid == 0 && (i + 2) < nIters) {
            asm volatile("fence.proxy.async.shared::cta;" ::: "memory");
            const long long cn = (long long)bid + (long long)(i + 2) * GRID_BLOCKS;
            const uint32_t mb = b ? mb1 : mb0;
            mbar_expect_tx(mb, CHUNK_BYTES);
            tma_bulk_1d(smem_u32(&buf[b][0]), coeffs + cn * CHUNK_FLOATS,
                        CHUNK_BYTES, mb);
        }
    }
}

extern "C" void kernel_launch(void* const* d_in, const int* in_sizes, int n_in,
                              void* d_out, int out_size) {
    const float* x      = (const float*)d_in[0];   // (6,)
    const float* coeffs = (const float*)d_in[1];   // (2048, 2048, 84)
    float* out = (float*)d_out;                    // (2048, 2048)

    monomial_matvec_kernel<<<GRID_BLOCKS, THREADS>>>(x, coeffs, out);
}